// round 1
// baseline (speedup 1.0000x reference)
#include <cuda_runtime.h>
#include <cuda_bf16.h>

// MergedEmbeddingBag: weights [T,N,D] f32, indices [T,TOTAL] i32, offsets [T,B] i32
// out [T,B,D] f32, sum pooling, include_last_offset=False.
// T=8, N=100000, D=128, B=16384, L=20 (TOTAL=327680) per the reference.

#define EB_T 8
#define EB_N 100000
#define EB_D 128
#define EB_B 16384
#define EB_MAXL 64   // staging capacity for per-bag indices (actual L=20)

__global__ void __launch_bounds__(EB_D, 8)
merged_embeddingbag_kernel(const float* __restrict__ weights,
                           const int* __restrict__ indices,
                           const int* __restrict__ offsets,
                           float* __restrict__ out,
                           int total_per_table)
{
    const int bag = blockIdx.x;
    const int tbl = blockIdx.y;
    const int tid = threadIdx.x;

    const int* off_t = offsets + (size_t)tbl * EB_B;
    const int start = off_t[bag];
    const int end   = (bag + 1 < EB_B) ? off_t[bag + 1] : total_per_table;
    int cnt = end - start;
    if (cnt < 0) cnt = 0;

    const int* idx_t = indices + (size_t)tbl * total_per_table + start;
    const float* w_t = weights + (size_t)tbl * EB_N * EB_D;

    __shared__ int sidx[EB_MAXL];
    const int staged = (cnt < EB_MAXL) ? cnt : EB_MAXL;
    for (int j = tid; j < staged; j += blockDim.x)
        sidx[j] = idx_t[j];
    __syncthreads();

    float sum = 0.0f;
    // Independent gathers (indices already in shared) -> high MLP to hide
    // L2/DRAM latency. All 128 threads read consecutive floats of one row:
    // 4x128B sectors, perfectly coalesced.
    #pragma unroll 5
    for (int j = 0; j < staged; j++) {
        sum += __ldg(&w_t[(size_t)sidx[j] * EB_D + tid]);
    }
    // Spill path (not expected for L=20, kept for semantic safety)
    for (int j = staged; j < cnt; j++) {
        sum += __ldg(&w_t[(size_t)idx_t[j] * EB_D + tid]);
    }

    out[((size_t)tbl * EB_B + bag) * (size_t)EB_D + tid] = sum;
}

extern "C" void kernel_launch(void* const* d_in, const int* in_sizes, int n_in,
                              void* d_out, int out_size)
{
    const float* weights = (const float*)d_in[0];
    const int*   indices = (const int*)d_in[1];
    const int*   offsets = (const int*)d_in[2];
    float*       out     = (float*)d_out;

    const int total_per_table = in_sizes[1] / EB_T;  // TOTAL = B*L = 327680

    dim3 grid(EB_B, EB_T);
    merged_embeddingbag_kernel<<<grid, EB_D>>>(weights, indices, offsets, out,
                                               total_per_table);
}

// round 2
// speedup vs baseline: 2.7743x; 2.7743x over previous
#include <cuda_runtime.h>
#include <cuda_bf16.h>

// MergedEmbeddingBag: weights [T,N,D] f32, indices [T,TOTAL] i32, offsets [T,B] i32
// out [T,B,D] f32, sum pooling. T=8, N=100000, D=128, B=16384, L=20.
//
// Warp-per-bag design: lane j holds index j (broadcast via shfl), each lane
// gathers one float4 of the row (LDG.128, perfectly coalesced 512B/warp).
// No shared memory, no block barriers -> warps are fully independent and the
// memory pipe stays saturated.

#define EB_T 8
#define EB_N 100000
#define EB_D 128
#define EB_B 16384
#define EB_LOG2_B 14
#define FULLMASK 0xffffffffu

__global__ void __launch_bounds__(256, 4)
merged_embeddingbag_warp_kernel(const float* __restrict__ weights,
                                const int* __restrict__ indices,
                                const int* __restrict__ offsets,
                                float* __restrict__ out,
                                int total_per_table)
{
    const int gw   = blockIdx.x * (blockDim.x >> 5) + (threadIdx.x >> 5); // global warp = (tbl,bag)
    const int lane = threadIdx.x & 31;
    const int tbl  = gw >> EB_LOG2_B;
    const int bag  = gw & (EB_B - 1);

    const int* off_t = offsets + tbl * EB_B;
    const int start = __ldg(&off_t[bag]);
    const int end   = (bag + 1 < EB_B) ? __ldg(&off_t[bag + 1]) : total_per_table;
    int cnt = end - start;
    if (cnt < 0) cnt = 0;

    const int* idx_t = indices + (size_t)tbl * total_per_table + start;
    const float4* __restrict__ w4 =
        (const float4*)(weights + (size_t)tbl * EB_N * EB_D);

    float4 acc = make_float4(0.f, 0.f, 0.f, 0.f);

    for (int base = 0; base < cnt; base += 32) {
        const int m = min(32, cnt - base);
        // lane j owns index (base+j); single coalesced load, no smem, no sync
        const int myidx = (lane < m) ? __ldg(&idx_t[base + lane]) : 0;

        if (m == 20) {
            // Hot path (fixed bag size L=20): full unroll -> ~20 independent
            // LDG.128 in flight per warp.
            #pragma unroll
            for (int j = 0; j < 20; j++) {
                const int r = __shfl_sync(FULLMASK, myidx, j);
                const float4 v = __ldg(&w4[r * 32 + lane]);
                acc.x += v.x; acc.y += v.y; acc.z += v.z; acc.w += v.w;
            }
        } else {
            for (int j = 0; j < m; j++) {
                const int r = __shfl_sync(FULLMASK, myidx, j);
                const float4 v = __ldg(&w4[r * 32 + lane]);
                acc.x += v.x; acc.y += v.y; acc.z += v.z; acc.w += v.w;
            }
        }
    }

    float4* __restrict__ o4 = (float4*)out;
    o4[(size_t)gw * 32 + lane] = acc;
}

extern "C" void kernel_launch(void* const* d_in, const int* in_sizes, int n_in,
                              void* d_out, int out_size)
{
    const float* weights = (const float*)d_in[0];
    const int*   indices = (const int*)d_in[1];
    const int*   offsets = (const int*)d_in[2];
    float*       out     = (float*)d_out;

    const int total_per_table = in_sizes[1] / EB_T;  // 327680

    const int warps_per_block = 8;                   // 256 threads
    const int total_warps = EB_T * EB_B;             // 131072 bags
    const int nblocks = total_warps / warps_per_block;

    merged_embeddingbag_warp_kernel<<<nblocks, warps_per_block * 32>>>(
        weights, indices, offsets, out, total_per_table);
}